// round 16
// baseline (speedup 1.0000x reference)
#include <cuda_runtime.h>
#include <cuda_bf16.h>

#define BATCH 16384
#define CTX 10
#define EMB 256

// TERMINAL KERNEL (R8 config; best measured: 42.62us wall / 42.40us ncu).
//
// One warp per (batch-element, sign) pair; 3-row-deep software pipeline of
// LDG.128 row loads; 64-reg budget (min-blocks=4); per-block atomic into out;
// accumulator zeroed by a graph memset node.
//
// Roofline argument (validated over 15 rounds):
//  - DRAM traffic ~255 MB = 196 MB unique-row floor + 0.36 L2-capacity miss
//    rate on 164 MB of duplicate rows (196 MB live set > 126 MB L2) —
//    schedule-invariant for i.i.d. indices.
//  - Delivered 6.0-6.2 TB/s = random-1KB-read HBM3e efficiency ceiling;
//    LTS cap is path-independent (TMA gather would hit the same wall).
//  - Isolated and rejected: eviction hints, LDG.256, deeper pipelines,
//    pos/neg fusion, persistent grid, in-kernel finalize, index hoisting,
//    sort-based reordering (doubles LTS traffic).
__global__ __launch_bounds__(256, 4) void cbow_loss_kernel(
    const int* __restrict__ pos_u,
    const int* __restrict__ pos_w,
    const int* __restrict__ neg_u,
    const int* __restrict__ neg_w,
    const float* __restrict__ u_weight,
    const float* __restrict__ w_weight,
    float* __restrict__ out)
{
    const int tid = blockIdx.x * blockDim.x + threadIdx.x;
    const int warp_id = tid >> 5;
    const int lane = threadIdx.x & 31;

    int b = warp_id;
    const bool is_neg = (b >= BATCH);
    if (is_neg) b -= BATCH;

    const int* __restrict__ uidx = is_neg ? neg_u : pos_u;
    const int* __restrict__ widx = is_neg ? neg_w : pos_w;

    // w-row loads issued immediately
    const long long wrow = (long long)__ldg(&widx[b]) * EMB;
    const float4* __restrict__ wr = reinterpret_cast<const float4*>(w_weight + wrow);
    const float4 w0 = __ldg(&wr[lane]);
    const float4 w1 = __ldg(&wr[lane + 32]);

    // all 10 context indices up front
    int ui[CTX];
    #pragma unroll
    for (int c = 0; c < CTX; c++)
        ui[c] = __ldg(&uidx[b * CTX + c]);

    #define UROW(c) (reinterpret_cast<const float4*>(u_weight + (long long)ui[(c)] * EMB))

    // 3-deep pipeline: rows c, c+1 resident, c+2 prefetching
    float4 a0 = __ldg(&UROW(0)[lane]);
    float4 a1 = __ldg(&UROW(0)[lane + 32]);
    float4 b0 = __ldg(&UROW(1)[lane]);
    float4 b1 = __ldg(&UROW(1)[lane + 32]);

    float acc = 0.0f;

    #pragma unroll
    for (int c = 0; c < CTX; c++) {
        float4 n0, n1;
        if (c + 2 < CTX) {
            n0 = __ldg(&UROW(c + 2)[lane]);
            n1 = __ldg(&UROW(c + 2)[lane + 32]);
        }
        acc = fmaf(a0.x, w0.x, acc);
        acc = fmaf(a0.y, w0.y, acc);
        acc = fmaf(a0.z, w0.z, acc);
        acc = fmaf(a0.w, w0.w, acc);
        acc = fmaf(a1.x, w1.x, acc);
        acc = fmaf(a1.y, w1.y, acc);
        acc = fmaf(a1.z, w1.z, acc);
        acc = fmaf(a1.w, w1.w, acc);
        a0 = b0; a1 = b1;
        b0 = n0; b1 = n1;
    }
    #undef UROW

    // warp reduce
    #pragma unroll
    for (int off = 16; off > 0; off >>= 1)
        acc += __shfl_xor_sync(0xFFFFFFFFu, acc, off);

    __shared__ float warp_part[8];
    if (lane == 0) {
        float s = is_neg ? -acc : acc;
        // log_sigmoid(s) = min(s,0) - log1p(exp(-|s|))
        float ls = fminf(s, 0.0f) - log1pf(__expf(-fabsf(s)));
        warp_part[threadIdx.x >> 5] = -ls;
    }
    __syncthreads();

    if (threadIdx.x == 0) {
        float blk = 0.0f;
        #pragma unroll
        for (int w = 0; w < 8; w++) blk += warp_part[w];
        atomicAdd(out, blk);
    }
}

extern "C" void kernel_launch(void* const* d_in, const int* in_sizes, int n_in,
                              void* d_out, int out_size) {
    const int*   pos_u    = (const int*)d_in[0];
    const int*   pos_w    = (const int*)d_in[1];
    const int*   neg_u    = (const int*)d_in[2];
    const int*   neg_w    = (const int*)d_in[3];
    const float* u_weight = (const float*)d_in[4];
    const float* w_weight = (const float*)d_in[5];
    float* out = (float*)d_out;

    // zero the accumulator via a graph memset node (cheapest option, R8-verified)
    cudaMemsetAsync(out, 0, sizeof(float));

    const int total_warps = 2 * BATCH;
    const int blocks = total_warps / 8;  // 4096
    cbow_loss_kernel<<<blocks, 256>>>(pos_u, pos_w, neg_u, neg_w,
                                      u_weight, w_weight, out);
}

// round 17
// speedup vs baseline: 1.0136x; 1.0136x over previous
#include <cuda_runtime.h>
#include <cuda_bf16.h>

#define BATCH 16384
#define CTX 10
#define EMB 256

// TERMINAL KERNEL (R8 config; best measured: 42.62us wall / 42.40us ncu).
//
// One warp per (batch-element, sign) pair; 3-row-deep software pipeline of
// LDG.128 row loads; 64-reg budget (min-blocks=4); per-block atomic into out;
// accumulator zeroed by a graph memset node.
//
// Roofline argument (validated over 16 rounds):
//  - DRAM traffic ~255 MB = 196 MB unique-row floor + 0.36 L2-capacity miss
//    rate on 164 MB of duplicate rows (196 MB live set > 126 MB L2) —
//    schedule-invariant for i.i.d. indices.
//  - Delivered 6.0-6.2 TB/s = random-1KB-read HBM3e efficiency ceiling;
//    LTS cap is path-independent (TMA gather would hit the same wall).
//  - Isolated and rejected: eviction hints, LDG.256, deeper pipelines,
//    pos/neg fusion, persistent grid, in-kernel finalize, index hoisting,
//    sort-based reordering (doubles LTS traffic).
__global__ __launch_bounds__(256, 4) void cbow_loss_kernel(
    const int* __restrict__ pos_u,
    const int* __restrict__ pos_w,
    const int* __restrict__ neg_u,
    const int* __restrict__ neg_w,
    const float* __restrict__ u_weight,
    const float* __restrict__ w_weight,
    float* __restrict__ out)
{
    const int tid = blockIdx.x * blockDim.x + threadIdx.x;
    const int warp_id = tid >> 5;
    const int lane = threadIdx.x & 31;

    int b = warp_id;
    const bool is_neg = (b >= BATCH);
    if (is_neg) b -= BATCH;

    const int* __restrict__ uidx = is_neg ? neg_u : pos_u;
    const int* __restrict__ widx = is_neg ? neg_w : pos_w;

    // w-row loads issued immediately
    const long long wrow = (long long)__ldg(&widx[b]) * EMB;
    const float4* __restrict__ wr = reinterpret_cast<const float4*>(w_weight + wrow);
    const float4 w0 = __ldg(&wr[lane]);
    const float4 w1 = __ldg(&wr[lane + 32]);

    // all 10 context indices up front
    int ui[CTX];
    #pragma unroll
    for (int c = 0; c < CTX; c++)
        ui[c] = __ldg(&uidx[b * CTX + c]);

    #define UROW(c) (reinterpret_cast<const float4*>(u_weight + (long long)ui[(c)] * EMB))

    // 3-deep pipeline: rows c, c+1 resident, c+2 prefetching
    float4 a0 = __ldg(&UROW(0)[lane]);
    float4 a1 = __ldg(&UROW(0)[lane + 32]);
    float4 b0 = __ldg(&UROW(1)[lane]);
    float4 b1 = __ldg(&UROW(1)[lane + 32]);

    float acc = 0.0f;

    #pragma unroll
    for (int c = 0; c < CTX; c++) {
        float4 n0, n1;
        if (c + 2 < CTX) {
            n0 = __ldg(&UROW(c + 2)[lane]);
            n1 = __ldg(&UROW(c + 2)[lane + 32]);
        }
        acc = fmaf(a0.x, w0.x, acc);
        acc = fmaf(a0.y, w0.y, acc);
        acc = fmaf(a0.z, w0.z, acc);
        acc = fmaf(a0.w, w0.w, acc);
        acc = fmaf(a1.x, w1.x, acc);
        acc = fmaf(a1.y, w1.y, acc);
        acc = fmaf(a1.z, w1.z, acc);
        acc = fmaf(a1.w, w1.w, acc);
        a0 = b0; a1 = b1;
        b0 = n0; b1 = n1;
    }
    #undef UROW

    // warp reduce
    #pragma unroll
    for (int off = 16; off > 0; off >>= 1)
        acc += __shfl_xor_sync(0xFFFFFFFFu, acc, off);

    __shared__ float warp_part[8];
    if (lane == 0) {
        float s = is_neg ? -acc : acc;
        // log_sigmoid(s) = min(s,0) - log1p(exp(-|s|))
        float ls = fminf(s, 0.0f) - log1pf(__expf(-fabsf(s)));
        warp_part[threadIdx.x >> 5] = -ls;
    }
    __syncthreads();

    if (threadIdx.x == 0) {
        float blk = 0.0f;
        #pragma unroll
        for (int w = 0; w < 8; w++) blk += warp_part[w];
        atomicAdd(out, blk);
    }
}

extern "C" void kernel_launch(void* const* d_in, const int* in_sizes, int n_in,
                              void* d_out, int out_size) {
    const int*   pos_u    = (const int*)d_in[0];
    const int*   pos_w    = (const int*)d_in[1];
    const int*   neg_u    = (const int*)d_in[2];
    const int*   neg_w    = (const int*)d_in[3];
    const float* u_weight = (const float*)d_in[4];
    const float* w_weight = (const float*)d_in[5];
    float* out = (float*)d_out;

    // zero the accumulator via a graph memset node (cheapest option, R8-verified)
    cudaMemsetAsync(out, 0, sizeof(float));

    const int total_warps = 2 * BATCH;
    const int blocks = total_warps / 8;  // 4096
    cbow_loss_kernel<<<blocks, 256>>>(pos_u, pos_w, neg_u, neg_w,
                                      u_weight, w_weight, out);
}